// round 1
// baseline (speedup 1.0000x reference)
#include <cuda_runtime.h>
#include <cuda_fp16.h>
#include <mma.h>
#include <math.h>

using namespace nvcuda;

#define TT 4096
#define HH 2048
#define EE 32
#define II 1024
#define TOPK 8
#define SIc 2048           // shared intermediate
#define NGU 2048           // 2*I
#define NGUS 4096          // 2*SI
#define TROWS (TT * TOPK)  // 32768 total routed rows
#define PROWS (TROWS + 128)
#define MAXTILES 288       // sum ceil(cnt_e/128) <= 256 + 32

// ---------------- static device scratch (no allocation allowed) ----------------
__device__ float g_logits[TT * EE];
__device__ int   g_cnt[EE];
__device__ int   g_rowOff[EE + 1];
__device__ int   g_tileOff[EE + 1];
__device__ int   g_slot_e[TT * TOPK];
__device__ int   g_slot_pos[TT * TOPK];
__device__ int   g_bucket_tok[EE * TT];
__device__ float g_bucket_w[EE * TT];
__device__ __align__(16) __half g_gu_r[(size_t)PROWS * NGU];   // 134 MB
__device__ __align__(16) __half g_h_r[(size_t)PROWS * II];     // 67 MB
__device__ __align__(16) float  g_y_r[(size_t)PROWS * HH];     // 269 MB
__device__ __align__(16) __half g_gu_s[(size_t)TT * NGUS];     // 33.5 MB
__device__ __align__(16) __half g_h_s[(size_t)TT * SIc];       // 16.8 MB

// ---------------- misc small kernels ----------------
__global__ void zero_cnt_kernel() {
    if (threadIdx.x < EE) g_cnt[threadIdx.x] = 0;
}

__global__ void prefix_kernel() {
    if (threadIdx.x == 0) {
        int ro = 0, to = 0;
        for (int e = 0; e < EE; e++) {
            g_rowOff[e] = ro;
            g_tileOff[e] = to;
            ro += g_cnt[e];
            to += (g_cnt[e] + 127) >> 7;
        }
        g_rowOff[EE] = ro;
        g_tileOff[EE] = to;
    }
}

// ---------------- router GEMM: logits[T,32] = X[T,H] @ Gw[H,32] ----------------
__global__ __launch_bounds__(256) void router_gemm_kernel(
    const float* __restrict__ x, const float* __restrict__ gw)
{
    __shared__ float As[64][33];  // [k][token]
    __shared__ float Bs[64][33];  // [k][expert]
    int m0 = blockIdx.x * 32;
    int tid = threadIdx.x;
    int t2 = (tid & 15) * 2;
    int e2 = (tid >> 4) * 2;
    float a00 = 0.f, a01 = 0.f, a10 = 0.f, a11 = 0.f;

    for (int k0 = 0; k0 < HH; k0 += 64) {
        // A: 32 rows x 64 cols, transposed into As[k][t]
        #pragma unroll
        for (int p = 0; p < 2; p++) {
            int idx = tid + p * 256;
            int r = idx >> 4;
            int c4 = (idx & 15) * 4;
            float4 v = *(const float4*)(x + (size_t)(m0 + r) * HH + k0 + c4);
            As[c4 + 0][r] = v.x; As[c4 + 1][r] = v.y;
            As[c4 + 2][r] = v.z; As[c4 + 3][r] = v.w;
        }
        // B: 64 rows x 32 cols
        #pragma unroll
        for (int p = 0; p < 2; p++) {
            int idx = tid + p * 256;
            int r = idx >> 3;
            int c4 = (idx & 7) * 4;
            float4 v = *(const float4*)(gw + (size_t)(k0 + r) * EE + c4);
            Bs[r][c4 + 0] = v.x; Bs[r][c4 + 1] = v.y;
            Bs[r][c4 + 2] = v.z; Bs[r][c4 + 3] = v.w;
        }
        __syncthreads();
        #pragma unroll 8
        for (int k = 0; k < 64; k++) {
            float x0 = As[k][t2], x1 = As[k][t2 + 1];
            float b0 = Bs[k][e2], b1 = Bs[k][e2 + 1];
            a00 += x0 * b0; a01 += x0 * b1;
            a10 += x1 * b0; a11 += x1 * b1;
        }
        __syncthreads();
    }
    g_logits[(size_t)(m0 + t2) * EE + e2]     = a00;
    g_logits[(size_t)(m0 + t2) * EE + e2 + 1] = a01;
    g_logits[(size_t)(m0 + t2 + 1) * EE + e2]     = a10;
    g_logits[(size_t)(m0 + t2 + 1) * EE + e2 + 1] = a11;
}

// ---------------- grouped top-k + bucketing ----------------
__global__ void topk_kernel(const float* __restrict__ bias) {
    int t = blockIdx.x * blockDim.x + threadIdx.x;
    if (t >= TT) return;

    float sco[EE], scb[EE];
    #pragma unroll
    for (int e = 0; e < EE; e++) {
        float l = g_logits[(size_t)t * EE + e];
        float s = 1.0f / (1.0f + expf(-l));
        sco[e] = s;
        scb[e] = s + bias[e];
    }
    // group scores: sum of top-2 of 4 per group
    float gs[8];
    #pragma unroll
    for (int g = 0; g < 8; g++) {
        int b = g * 4;
        float m1 = scb[b], m2 = -1e30f;
        #pragma unroll
        for (int i = 1; i < 4; i++) {
            float v = scb[b + i];
            if (v > m1) { m2 = m1; m1 = v; }
            else if (v > m2) { m2 = v; }
        }
        gs[g] = m1 + m2;
    }
    // top-4 groups (strict >, lowest index on tie)
    bool gsel[8];
    #pragma unroll
    for (int g = 0; g < 8; g++) gsel[g] = false;
    for (int it = 0; it < 4; it++) {
        float best = -1e30f; int bi = -1;
        #pragma unroll
        for (int g = 0; g < 8; g++)
            if (!gsel[g] && gs[g] > best) { best = gs[g]; bi = g; }
        gsel[bi] = true;
    }
    // mask, then top-8 experts
    float msk[EE];
    #pragma unroll
    for (int e = 0; e < EE; e++) msk[e] = gsel[e >> 2] ? scb[e] : -1e30f;
    int ids[TOPK]; float ws[TOPK]; float wsum = 0.f;
    for (int it = 0; it < TOPK; it++) {
        float best = -1e30f; int bi = 0;
        #pragma unroll
        for (int e = 0; e < EE; e++)
            if (msk[e] > best) { best = msk[e]; bi = e; }
        msk[bi] = -1e30f;
        ids[it] = bi;
        ws[it] = sco[bi];
        wsum += ws[it];
    }
    float inv = 1.0f / (wsum + 1e-20f);
    #pragma unroll
    for (int k = 0; k < TOPK; k++) {
        int e = ids[k];
        float w = ws[k] * inv;
        int pos = atomicAdd(&g_cnt[e], 1);
        g_slot_e[t * TOPK + k] = e;
        g_slot_pos[t * TOPK + k] = pos;
        g_bucket_tok[e * TT + pos] = t;
        g_bucket_w[e * TT + pos] = w;
    }
}

// ---------------- unified tiled fp16 wmma GEMM ----------------
// EPI: 0 = store half (gu scratch), 1 = store float * 2.5*w (Y scratch), 2 = store float (d_out)
template<bool ROUTED, bool AHALF, int EPI>
__global__ __launch_bounds__(256) void mm_kernel(
    const float* __restrict__ Af, const float* __restrict__ B0,
    size_t Bstride, int K, int N, int M_dense, float* __restrict__ outArg)
{
    __shared__ __align__(16) __half As[128][40];
    __shared__ __align__(16) __half Bs[32][136];

    int tid = threadIdx.x;
    int e = 0, m0, Mrows, rbase;
    const float* B;
    if (ROUTED) {
        int tlin = blockIdx.x;
        if (tlin >= g_tileOff[EE]) return;
        while (g_tileOff[e + 1] <= tlin) e++;
        m0 = (tlin - g_tileOff[e]) * 128;
        Mrows = g_cnt[e];
        B = B0 + (size_t)e * Bstride;
        rbase = g_rowOff[e];
    } else {
        m0 = blockIdx.x * 128;
        Mrows = M_dense;
        B = B0;
        rbase = 0;
    }
    int n0 = blockIdx.y * 128;

    const __half* Ah = ROUTED ? g_h_r : g_h_s;
    __half* outH = ROUTED ? g_gu_r : g_gu_s;
    float* outF = (EPI == 1) ? g_y_r : outArg;
    int ldO = (EPI == 0) ? (ROUTED ? NGU : NGUS) : HH;

    int wid = tid >> 5;
    int wm = wid & 1;
    int wn = wid >> 1;

    wmma::fragment<wmma::accumulator, 16, 16, 16, float> acc[4][2];
    #pragma unroll
    for (int i = 0; i < 4; i++)
        #pragma unroll
        for (int j = 0; j < 2; j++)
            wmma::fill_fragment(acc[i][j], 0.0f);

    for (int k0 = 0; k0 < K; k0 += 32) {
        if (AHALF) {
            int c8 = (tid & 3) * 8;
            int rs = tid >> 2;  // 0..63
            #pragma unroll
            for (int p = 0; p < 2; p++) {
                int r = rs + p * 64;
                const __half* src = Ah + (size_t)(rbase + m0 + r) * K + k0 + c8;
                uint4 v = *(const uint4*)src;
                *(uint4*)&As[r][c8] = v;
            }
        } else {
            int c4 = (tid & 7) * 4;
            int rs = tid >> 3;  // 0..31
            #pragma unroll
            for (int p = 0; p < 4; p++) {
                int r = rs + p * 32;
                float4 v = make_float4(0.f, 0.f, 0.f, 0.f);
                if (m0 + r < Mrows) {
                    size_t arow = ROUTED ? (size_t)g_bucket_tok[e * TT + m0 + r]
                                         : (size_t)(m0 + r);
                    v = *(const float4*)(Af + arow * (size_t)K + k0 + c4);
                }
                As[r][c4 + 0] = __float2half_rn(v.x);
                As[r][c4 + 1] = __float2half_rn(v.y);
                As[r][c4 + 2] = __float2half_rn(v.z);
                As[r][c4 + 3] = __float2half_rn(v.w);
            }
        }
        {
            int c4 = (tid & 31) * 4;
            int rs = tid >> 5;  // 0..7
            #pragma unroll
            for (int p = 0; p < 4; p++) {
                int r = rs + p * 8;
                float4 v = *(const float4*)(B + (size_t)(k0 + r) * N + n0 + c4);
                Bs[r][c4 + 0] = __float2half_rn(v.x);
                Bs[r][c4 + 1] = __float2half_rn(v.y);
                Bs[r][c4 + 2] = __float2half_rn(v.z);
                Bs[r][c4 + 3] = __float2half_rn(v.w);
            }
        }
        __syncthreads();
        #pragma unroll
        for (int kk = 0; kk < 32; kk += 16) {
            wmma::fragment<wmma::matrix_a, 16, 16, 16, __half, wmma::row_major> af[4];
            wmma::fragment<wmma::matrix_b, 16, 16, 16, __half, wmma::row_major> bf[2];
            #pragma unroll
            for (int i = 0; i < 4; i++)
                wmma::load_matrix_sync(af[i], &As[wm * 64 + i * 16][kk], 40);
            #pragma unroll
            for (int j = 0; j < 2; j++)
                wmma::load_matrix_sync(bf[j], &Bs[kk][wn * 32 + j * 16], 136);
            #pragma unroll
            for (int i = 0; i < 4; i++)
                #pragma unroll
                for (int j = 0; j < 2; j++)
                    wmma::mma_sync(acc[i][j], af[i], bf[j], acc[i][j]);
        }
        __syncthreads();
    }

    // epilogue via per-warp smem patch (reuse As memory: 8 warps * 320 floats = 10240B)
    float* patch = reinterpret_cast<float*>(&As[0][0]) + wid * 320;
    int lane = tid & 31;
    #pragma unroll
    for (int i = 0; i < 4; i++) {
        #pragma unroll
        for (int j = 0; j < 2; j++) {
            wmma::store_matrix_sync(patch, acc[i][j], 20, wmma::mem_row_major);
            __syncwarp();
            #pragma unroll
            for (int s = 0; s < 8; s++) {
                int idx = lane + s * 32;
                int r = idx >> 4, c = idx & 15;
                int ml = m0 + wm * 64 + i * 16 + r;
                if (ml < Mrows) {
                    int col = n0 + wn * 32 + j * 16 + c;
                    float v = patch[r * 20 + c];
                    size_t o = (size_t)(rbase + ml) * ldO + col;
                    if (EPI == 0) outH[o] = __float2half_rn(v);
                    else if (EPI == 1) outF[o] = v * (2.5f * g_bucket_w[e * TT + ml]);
                    else outF[o] = v;
                }
            }
            __syncwarp();
        }
    }
}

// ---------------- activation: h = silu(gu[:, :I]) * gu[:, I:] ----------------
__global__ __launch_bounds__(256) void act_routed_kernel() {
    long idx = (long)blockIdx.x * 256 + threadIdx.x;  // over TROWS * II/2
    int row = (int)(idx >> 9);
    int j2 = (int)(idx & 511) << 1;
    float2 g = __half22float2(*(const __half2*)(g_gu_r + (size_t)row * NGU + j2));
    float2 u = __half22float2(*(const __half2*)(g_gu_r + (size_t)row * NGU + II + j2));
    float h0 = g.x / (1.0f + __expf(-g.x)) * u.x;
    float h1 = g.y / (1.0f + __expf(-g.y)) * u.y;
    *((__half2*)(g_h_r + (size_t)row * II + j2)) = __floats2half2_rn(h0, h1);
}

__global__ __launch_bounds__(256) void act_shared_kernel() {
    long idx = (long)blockIdx.x * 256 + threadIdx.x;  // over TT * SI/2
    int row = (int)(idx >> 10);
    int j2 = (int)(idx & 1023) << 1;
    float2 g = __half22float2(*(const __half2*)(g_gu_s + (size_t)row * NGUS + j2));
    float2 u = __half22float2(*(const __half2*)(g_gu_s + (size_t)row * NGUS + SIc + j2));
    float h0 = g.x / (1.0f + __expf(-g.x)) * u.x;
    float h1 = g.y / (1.0f + __expf(-g.y)) * u.y;
    *((__half2*)(g_h_s + (size_t)row * SIc + j2)) = __floats2half2_rn(h0, h1);
}

// ---------------- combine: out[t] = shared[t] + sum_k Y[row_k] ----------------
__global__ __launch_bounds__(256) void combine_kernel(float* __restrict__ out) {
    int t = blockIdx.x;
    int rows[TOPK];
    #pragma unroll
    for (int k = 0; k < TOPK; k++) {
        int e = g_slot_e[t * TOPK + k];
        rows[k] = g_rowOff[e] + g_slot_pos[t * TOPK + k];
    }
    for (int c = threadIdx.x; c < HH; c += 256) {
        float s = out[(size_t)t * HH + c];
        #pragma unroll
        for (int k = 0; k < TOPK; k++)
            s += g_y_r[(size_t)rows[k] * HH + c];
        out[(size_t)t * HH + c] = s;
    }
}

// ---------------- launch ----------------
extern "C" void kernel_launch(void* const* d_in, const int* in_sizes, int n_in,
                              void* d_out, int out_size)
{
    const float* hidden = (const float*)d_in[0];
    const float* gate_w = (const float*)d_in[1];
    const float* gate_b = (const float*)d_in[2];
    const float* w_gu   = (const float*)d_in[3];
    const float* w_dn   = (const float*)d_in[4];
    const float* s_gu   = (const float*)d_in[5];
    const float* s_dn   = (const float*)d_in[6];
    float* out = (float*)d_out;

    zero_cnt_kernel<<<1, 32>>>();
    router_gemm_kernel<<<TT / 32, 256>>>(hidden, gate_w);
    topk_kernel<<<TT / 256, 256>>>(gate_b);
    prefix_kernel<<<1, 32>>>();

    // routed GEMM1: gu_r[rows,2048] = gather(X)[rows,2048] @ w_gate_up[e]
    mm_kernel<true, false, 0><<<dim3(MAXTILES, NGU / 128), 256>>>(
        hidden, w_gu, (size_t)HH * NGU, HH, NGU, 0, nullptr);
    // routed activation
    act_routed_kernel<<<(TROWS * (II / 2)) / 256, 256>>>();

    // shared GEMM1: gu_s[4096,4096] = X @ shared_gate_up
    mm_kernel<false, false, 0><<<dim3(TT / 128, NGUS / 128), 256>>>(
        hidden, s_gu, 0, HH, NGUS, TT, nullptr);
    act_shared_kernel<<<(TT * (SIc / 2)) / 256, 256>>>();

    // shared GEMM2 -> d_out (initializes every output element)
    mm_kernel<false, true, 2><<<dim3(TT / 128, HH / 128), 256>>>(
        nullptr, s_dn, 0, SIc, HH, TT, out);

    // routed GEMM2 -> Y (scaled by 2.5 * topk weight per row)
    mm_kernel<true, true, 1><<<dim3(MAXTILES, HH / 128), 256>>>(
        nullptr, w_dn, (size_t)II * HH, II, HH, 0, nullptr);

    // combine routed into d_out
    combine_kernel<<<TT, 256>>>(out);
}

// round 3
// speedup vs baseline: 1.3478x; 1.3478x over previous
#include <cuda_runtime.h>
#include <cuda_fp16.h>
#include <mma.h>
#include <math.h>
#include <cstdint>

using namespace nvcuda;

#define TT 4096
#define HH 2048
#define EE 32
#define II 1024
#define TOPK 8
#define SIc 2048           // shared intermediate
#define NGU 2048           // 2*I
#define NGUS 4096          // 2*SI
#define TROWS (TT * TOPK)  // 32768 total routed rows (counts always sum to this)
#define PROWS (TROWS + 128)
#define MAXTILES 288       // sum ceil(cnt_e/128) <= 256 + 32

// ---------------- static device scratch (no allocation allowed) ----------------
__device__ float g_logits[TT * EE];
__device__ int   g_cnt[EE];
__device__ int   g_rowOff[EE + 1];
__device__ int   g_tileOff[EE + 1];
__device__ int   g_slot_e[TT * TOPK];
__device__ int   g_slot_pos[TT * TOPK];
__device__ int   g_bucket_tok[EE * TT];
__device__ float g_bucket_w[EE * TT];

__device__ __align__(16) __half g_x_h[(size_t)TT * HH];          // 16 MB
__device__ __align__(16) __half g_wgu_h[(size_t)EE * HH * NGU];  // 268 MB
__device__ __align__(16) __half g_wdn_h[(size_t)EE * II * HH];   // 134 MB
__device__ __align__(16) __half g_sgu_h[(size_t)HH * NGUS];      // 33.5 MB
__device__ __align__(16) __half g_sdn_h[(size_t)SIc * HH];       // 16.8 MB

__device__ __align__(16) __half g_gu_r[(size_t)PROWS * NGU];     // 134 MB
__device__ __align__(16) __half g_h_r[(size_t)PROWS * II];       // 67 MB
__device__ __align__(16) float  g_y_r[(size_t)PROWS * HH];       // 269 MB
__device__ __align__(16) __half g_gu_s[(size_t)TT * NGUS];       // 33.5 MB
__device__ __align__(16) __half g_h_s[(size_t)TT * SIc];         // 16.8 MB

// ---------------- cp.async helpers ----------------
__device__ __forceinline__ void cp16(void* smem_dst, const void* gmem_src) {
    unsigned int d = (unsigned int)__cvta_generic_to_shared(smem_dst);
    asm volatile("cp.async.cg.shared.global [%0], [%1], 16;\n" :: "r"(d), "l"(gmem_src));
}
__device__ __forceinline__ void cp_commit() {
    asm volatile("cp.async.commit_group;\n");
}
template<int N>
__device__ __forceinline__ void cp_wait() {
    asm volatile("cp.async.wait_group %0;\n" :: "n"(N));
}

// ---------------- fp32 -> fp16 bulk convert ----------------
__global__ __launch_bounds__(256) void f2h_kernel(const float4* __restrict__ src,
                                                  __half* __restrict__ dst, long n4) {
    long stride = (long)gridDim.x * blockDim.x;
    for (long i = (long)blockIdx.x * blockDim.x + threadIdx.x; i < n4; i += stride) {
        float4 v = src[i];
        __half2 h0 = __floats2half2_rn(v.x, v.y);
        __half2 h1 = __floats2half2_rn(v.z, v.w);
        uint2 packed;
        packed.x = *(unsigned int*)&h0;
        packed.y = *(unsigned int*)&h1;
        *(uint2*)(dst + i * 4) = packed;
    }
}

// ---------------- misc small kernels ----------------
__global__ void zero_cnt_kernel() {
    if (threadIdx.x < EE) g_cnt[threadIdx.x] = 0;
}

__global__ void prefix_kernel() {
    if (threadIdx.x == 0) {
        int ro = 0, to = 0;
        for (int e = 0; e < EE; e++) {
            g_rowOff[e] = ro;
            g_tileOff[e] = to;
            ro += g_cnt[e];
            to += (g_cnt[e] + 127) >> 7;
        }
        g_rowOff[EE] = ro;
        g_tileOff[EE] = to;
    }
}

// ---------------- router GEMM: logits[T,32] = X[T,H] @ Gw[H,32] ----------------
__global__ __launch_bounds__(256) void router_gemm_kernel(
    const float* __restrict__ x, const float* __restrict__ gw)
{
    __shared__ float As[64][33];
    __shared__ float Bs[64][33];
    int m0 = blockIdx.x * 32;
    int tid = threadIdx.x;
    int t2 = (tid & 15) * 2;
    int e2 = (tid >> 4) * 2;
    float a00 = 0.f, a01 = 0.f, a10 = 0.f, a11 = 0.f;

    for (int k0 = 0; k0 < HH; k0 += 64) {
        #pragma unroll
        for (int p = 0; p < 2; p++) {
            int idx = tid + p * 256;
            int r = idx >> 4;
            int c4 = (idx & 15) * 4;
            float4 v = *(const float4*)(x + (size_t)(m0 + r) * HH + k0 + c4);
            As[c4 + 0][r] = v.x; As[c4 + 1][r] = v.y;
            As[c4 + 2][r] = v.z; As[c4 + 3][r] = v.w;
        }
        #pragma unroll
        for (int p = 0; p < 2; p++) {
            int idx = tid + p * 256;
            int r = idx >> 3;
            int c4 = (idx & 7) * 4;
            float4 v = *(const float4*)(gw + (size_t)(k0 + r) * EE + c4);
            Bs[r][c4 + 0] = v.x; Bs[r][c4 + 1] = v.y;
            Bs[r][c4 + 2] = v.z; Bs[r][c4 + 3] = v.w;
        }
        __syncthreads();
        #pragma unroll 8
        for (int k = 0; k < 64; k++) {
            float x0 = As[k][t2], x1 = As[k][t2 + 1];
            float b0 = Bs[k][e2], b1 = Bs[k][e2 + 1];
            a00 += x0 * b0; a01 += x0 * b1;
            a10 += x1 * b0; a11 += x1 * b1;
        }
        __syncthreads();
    }
    g_logits[(size_t)(m0 + t2) * EE + e2]     = a00;
    g_logits[(size_t)(m0 + t2) * EE + e2 + 1] = a01;
    g_logits[(size_t)(m0 + t2 + 1) * EE + e2]     = a10;
    g_logits[(size_t)(m0 + t2 + 1) * EE + e2 + 1] = a11;
}

// ---------------- grouped top-k + bucketing ----------------
__global__ void topk_kernel(const float* __restrict__ bias) {
    int t = blockIdx.x * blockDim.x + threadIdx.x;
    if (t >= TT) return;

    float sco[EE], scb[EE];
    #pragma unroll
    for (int e = 0; e < EE; e++) {
        float l = g_logits[(size_t)t * EE + e];
        float s = 1.0f / (1.0f + expf(-l));
        sco[e] = s;
        scb[e] = s + bias[e];
    }
    float gs[8];
    #pragma unroll
    for (int g = 0; g < 8; g++) {
        int b = g * 4;
        float m1 = scb[b], m2 = -1e30f;
        #pragma unroll
        for (int i = 1; i < 4; i++) {
            float v = scb[b + i];
            if (v > m1) { m2 = m1; m1 = v; }
            else if (v > m2) { m2 = v; }
        }
        gs[g] = m1 + m2;
    }
    bool gsel[8];
    #pragma unroll
    for (int g = 0; g < 8; g++) gsel[g] = false;
    for (int it = 0; it < 4; it++) {
        float best = -1e30f; int bi = -1;
        #pragma unroll
        for (int g = 0; g < 8; g++)
            if (!gsel[g] && gs[g] > best) { best = gs[g]; bi = g; }
        gsel[bi] = true;
    }
    float msk[EE];
    #pragma unroll
    for (int e = 0; e < EE; e++) msk[e] = gsel[e >> 2] ? scb[e] : -1e30f;
    int ids[TOPK]; float ws[TOPK]; float wsum = 0.f;
    for (int it = 0; it < TOPK; it++) {
        float best = -1e30f; int bi = 0;
        #pragma unroll
        for (int e = 0; e < EE; e++)
            if (msk[e] > best) { best = msk[e]; bi = e; }
        msk[bi] = -1e30f;
        ids[it] = bi;
        ws[it] = sco[bi];
        wsum += ws[it];
    }
    float inv = 1.0f / (wsum + 1e-20f);
    #pragma unroll
    for (int k = 0; k < TOPK; k++) {
        int e = ids[k];
        float w = ws[k] * inv;
        int pos = atomicAdd(&g_cnt[e], 1);
        g_slot_e[t * TOPK + k] = e;
        g_slot_pos[t * TOPK + k] = pos;
        g_bucket_tok[e * TT + pos] = t;
        g_bucket_w[e * TT + pos] = w;
    }
}

// ---------------- unified fp16 wmma GEMM, cp.async double-buffered ----------------
// EPI: 0 = store half to outH, 1 = store float*2.5*w to g_y_r, 2 = store float to outF
template<bool ROUTED, bool GATHER, int EPI>
__global__ __launch_bounds__(256) void mm_kernel(
    const __half* __restrict__ Ah, const __half* __restrict__ B0,
    size_t Bstride, int K, int N, int M_dense,
    __half* __restrict__ outH, float* __restrict__ outF, int ldO)
{
    __shared__ __align__(16) __half As[2][128][40];
    __shared__ __align__(16) __half Bs[2][32][136];

    int tid = threadIdx.x;
    int e = 0, m0, Mrows, rbase;
    const __half* B;
    if (ROUTED) {
        int tlin = blockIdx.x;
        if (tlin >= g_tileOff[EE]) return;
        while (g_tileOff[e + 1] <= tlin) e++;
        m0 = (tlin - g_tileOff[e]) * 128;
        Mrows = g_cnt[e];
        B = B0 + (size_t)e * Bstride;
        rbase = g_rowOff[e];
    } else {
        m0 = blockIdx.x * 128;
        Mrows = M_dense;
        B = B0;
        rbase = 0;
    }
    int n0 = blockIdx.y * 128;
    const __half* Bp = B + n0;

    // hoist A row source pointers (2 rows per thread)
    int rA = tid >> 2;            // 0..63
    int cA8 = (tid & 3) * 8;
    const __half* aptr[2];
    #pragma unroll
    for (int p = 0; p < 2; p++) {
        int r = rA + p * 64;
        size_t row;
        if (GATHER) {
            int ml = m0 + r;
            int tok = (ml < Mrows) ? g_bucket_tok[e * TT + ml] : 0;
            row = (size_t)(tok & (TT - 1));
        } else if (ROUTED) {
            row = (size_t)(rbase + m0 + r);
        } else {
            row = (size_t)(m0 + r);
        }
        aptr[p] = Ah + row * (size_t)K + cA8;
    }
    int rB = tid >> 4;            // 0..15
    int cB8 = (tid & 15) * 8;

    int steps = K >> 5;

    // prologue: stage 0
    {
        #pragma unroll
        for (int p = 0; p < 2; p++)
            cp16(&As[0][rA + p * 64][cA8], aptr[p]);
        #pragma unroll
        for (int p = 0; p < 2; p++) {
            int r = rB + p * 16;
            cp16(&Bs[0][r][cB8], Bp + (size_t)r * N + cB8);
        }
        cp_commit();
    }

    int wid = tid >> 5;
    int wm = wid & 1;
    int wn = wid >> 1;

    wmma::fragment<wmma::accumulator, 16, 16, 16, float> acc[4][2];
    #pragma unroll
    for (int i = 0; i < 4; i++)
        #pragma unroll
        for (int j = 0; j < 2; j++)
            wmma::fill_fragment(acc[i][j], 0.0f);

    for (int it = 0; it < steps; it++) {
        int cur = it & 1;
        if (it + 1 < steps) {
            int nxt = cur ^ 1;
            int k0 = (it + 1) << 5;
            #pragma unroll
            for (int p = 0; p < 2; p++)
                cp16(&As[nxt][rA + p * 64][cA8], aptr[p] + k0);
            #pragma unroll
            for (int p = 0; p < 2; p++) {
                int r = rB + p * 16;
                cp16(&Bs[nxt][r][cB8], Bp + (size_t)(k0 + r) * N + cB8);
            }
            cp_commit();
            cp_wait<1>();
        } else {
            cp_wait<0>();
        }
        __syncthreads();

        #pragma unroll
        for (int kk = 0; kk < 32; kk += 16) {
            wmma::fragment<wmma::matrix_a, 16, 16, 16, __half, wmma::row_major> af[4];
            wmma::fragment<wmma::matrix_b, 16, 16, 16, __half, wmma::row_major> bf[2];
            #pragma unroll
            for (int i = 0; i < 4; i++)
                wmma::load_matrix_sync(af[i], &As[cur][wm * 64 + i * 16][kk], 40);
            #pragma unroll
            for (int j = 0; j < 2; j++)
                wmma::load_matrix_sync(bf[j], &Bs[cur][kk][wn * 32 + j * 16], 136);
            #pragma unroll
            for (int i = 0; i < 4; i++)
                #pragma unroll
                for (int j = 0; j < 2; j++)
                    wmma::mma_sync(acc[i][j], af[i], bf[j], acc[i][j]);
        }
        __syncthreads();
    }

    // epilogue via per-warp smem patch
    float* patch = reinterpret_cast<float*>(&As[0][0][0]) + wid * 320;
    int lane = tid & 31;
    #pragma unroll
    for (int i = 0; i < 4; i++) {
        #pragma unroll
        for (int j = 0; j < 2; j++) {
            wmma::store_matrix_sync(patch, acc[i][j], 20, wmma::mem_row_major);
            __syncwarp();
            #pragma unroll
            for (int s = 0; s < 8; s++) {
                int idx = lane + s * 32;
                int r = idx >> 4, c = idx & 15;
                int ml = m0 + wm * 64 + i * 16 + r;
                if (ml < Mrows) {
                    int col = n0 + wn * 32 + j * 16 + c;
                    float v = patch[r * 20 + c];
                    size_t o = (size_t)(rbase + ml) * ldO + col;
                    if (EPI == 0) outH[o] = __float2half_rn(v);
                    else if (EPI == 1) outF[o] = v * (2.5f * g_bucket_w[e * TT + ml]);
                    else outF[o] = v;
                }
            }
            __syncwarp();
        }
    }
}

// ---------------- activation: h = silu(gu[:, :I]) * gu[:, I:] ----------------
__global__ __launch_bounds__(256) void act_routed_kernel() {
    long idx = (long)blockIdx.x * 256 + threadIdx.x;  // over TROWS * II/2
    int row = (int)(idx >> 9);
    int j2 = (int)(idx & 511) << 1;
    float2 g = __half22float2(*(const __half2*)(g_gu_r + (size_t)row * NGU + j2));
    float2 u = __half22float2(*(const __half2*)(g_gu_r + (size_t)row * NGU + II + j2));
    float h0 = g.x / (1.0f + __expf(-g.x)) * u.x;
    float h1 = g.y / (1.0f + __expf(-g.y)) * u.y;
    *((__half2*)(g_h_r + (size_t)row * II + j2)) = __floats2half2_rn(h0, h1);
}

__global__ __launch_bounds__(256) void act_shared_kernel() {
    long idx = (long)blockIdx.x * 256 + threadIdx.x;  // over TT * SI/2
    int row = (int)(idx >> 10);
    int j2 = (int)(idx & 1023) << 1;
    float2 g = __half22float2(*(const __half2*)(g_gu_s + (size_t)row * NGUS + j2));
    float2 u = __half22float2(*(const __half2*)(g_gu_s + (size_t)row * NGUS + SIc + j2));
    float h0 = g.x / (1.0f + __expf(-g.x)) * u.x;
    float h1 = g.y / (1.0f + __expf(-g.y)) * u.y;
    *((__half2*)(g_h_s + (size_t)row * SIc + j2)) = __floats2half2_rn(h0, h1);
}

// ---------------- combine: out[t] = shared[t] + sum_k Y[row_k] ----------------
__global__ __launch_bounds__(256) void combine_kernel(float* __restrict__ out) {
    int t = blockIdx.x;
    int rows[TOPK];
    #pragma unroll
    for (int k = 0; k < TOPK; k++) {
        int e = g_slot_e[t * TOPK + k];
        rows[k] = g_rowOff[e] + g_slot_pos[t * TOPK + k];
    }
    int c = threadIdx.x * 4;  // 256 threads * 4 floats = 1024 per iter
    #pragma unroll
    for (int rep = 0; rep < 2; rep++, c += 1024) {
        float4 s = *(float4*)(out + (size_t)t * HH + c);
        #pragma unroll
        for (int k = 0; k < TOPK; k++) {
            float4 y = *(const float4*)(g_y_r + (size_t)rows[k] * HH + c);
            s.x += y.x; s.y += y.y; s.z += y.z; s.w += y.w;
        }
        *(float4*)(out + (size_t)t * HH + c) = s;
    }
}

// ---------------- launch ----------------
extern "C" void kernel_launch(void* const* d_in, const int* in_sizes, int n_in,
                              void* d_out, int out_size)
{
    const float* hidden = (const float*)d_in[0];
    const float* gate_w = (const float*)d_in[1];
    const float* gate_b = (const float*)d_in[2];
    const float* w_gu   = (const float*)d_in[3];
    const float* w_dn   = (const float*)d_in[4];
    const float* s_gu   = (const float*)d_in[5];
    const float* s_dn   = (const float*)d_in[6];
    float* out = (float*)d_out;

    __half *x_h, *wgu_h, *wdn_h, *sgu_h, *sdn_h;
    cudaGetSymbolAddress((void**)&x_h,   g_x_h);
    cudaGetSymbolAddress((void**)&wgu_h, g_wgu_h);
    cudaGetSymbolAddress((void**)&wdn_h, g_wdn_h);
    cudaGetSymbolAddress((void**)&sgu_h, g_sgu_h);
    cudaGetSymbolAddress((void**)&sdn_h, g_sdn_h);
    __half *gu_r, *h_r, *gu_s, *h_s;
    float* y_r;
    cudaGetSymbolAddress((void**)&gu_r, g_gu_r);
    cudaGetSymbolAddress((void**)&h_r,  g_h_r);
    cudaGetSymbolAddress((void**)&y_r,  g_y_r);
    cudaGetSymbolAddress((void**)&gu_s, g_gu_s);
    cudaGetSymbolAddress((void**)&h_s,  g_h_s);

    const int CB = 1184;  // convert grid (148 SMs * 8)
    f2h_kernel<<<CB, 256>>>((const float4*)hidden, x_h,   (long)TT * HH / 4);
    f2h_kernel<<<CB, 256>>>((const float4*)w_gu,   wgu_h, (long)EE * HH * NGU / 4);
    f2h_kernel<<<CB, 256>>>((const float4*)w_dn,   wdn_h, (long)EE * II * HH / 4);
    f2h_kernel<<<CB, 256>>>((const float4*)s_gu,   sgu_h, (long)HH * NGUS / 4);
    f2h_kernel<<<CB, 256>>>((const float4*)s_dn,   sdn_h, (long)SIc * HH / 4);

    zero_cnt_kernel<<<1, 32>>>();
    router_gemm_kernel<<<TT / 32, 256>>>(hidden, gate_w);
    topk_kernel<<<TT / 256, 256>>>(gate_b);
    prefix_kernel<<<1, 32>>>();

    // routed GEMM1: gu_r[rows,2048] = gather(X_h)[rows,2048] @ wgu_h[e]
    mm_kernel<true, true, 0><<<dim3(MAXTILES, NGU / 128), 256>>>(
        x_h, wgu_h, (size_t)HH * NGU, HH, NGU, 0, gu_r, nullptr, NGU);
    act_routed_kernel<<<(TROWS * (II / 2)) / 256, 256>>>();

    // shared GEMM1: gu_s[4096,4096] = X_h @ sgu_h
    mm_kernel<false, false, 0><<<dim3(TT / 128, NGUS / 128), 256>>>(
        x_h, sgu_h, 0, HH, NGUS, TT, gu_s, nullptr, NGUS);
    act_shared_kernel<<<(TT * (SIc / 2)) / 256, 256>>>();

    // shared GEMM2 -> d_out (initializes every output element)
    mm_kernel<false, false, 2><<<dim3(TT / 128, HH / 128), 256>>>(
        h_s, sdn_h, 0, SIc, HH, TT, nullptr, out, HH);

    // routed GEMM2 -> Y (scaled by 2.5 * topk weight per row)
    mm_kernel<true, false, 1><<<dim3(MAXTILES, HH / 128), 256>>>(
        h_r, wdn_h, (size_t)II * HH, II, HH, 0, nullptr, y_r, HH);

    // combine routed into d_out
    combine_kernel<<<TT, 256>>>(out);
}